// round 13
// baseline (speedup 1.0000x reference)
#include <cuda_runtime.h>
#include <cuda_bf16.h>

#define NN 100000
#define NE 600000
#define NG 256
#define HID 128
#define BN_EPS 1e-5f

#define SCAN_TPB 512
#define SCAN_ELEMS 2048                       // 4 elems per thread
#define SCAN_NB ((NN + SCAN_ELEMS - 1) / SCAN_ELEMS)   // 49

// ---------------- scratch (device globals; no allocation allowed) ------------
__device__ float g_dinv[NN];
__device__ float g_hl[NN * HID];   // hl = h @ W
__device__ float g_h[NN * HID];    // layer activations
__device__ float g_lig[NG * HID];  // pooled per-graph embedding
__device__ float g_p[64];          // pocket MLP output
// CSR scratch
__device__ int g_cnt[NN];
__device__ int g_rowptr[NN];
__device__ int g_cur[NN];
__device__ int g_eidx[NE];         // src indices grouped by dst
__device__ int g_part[SCAN_NB];

// ================= CSR build (once per launch) ===============================
__global__ void k_zero_cnt() {
    int n = blockIdx.x * blockDim.x + threadIdx.x;
    if (n < NN) g_cnt[n] = 0;
}

__global__ void k_hist(const int* __restrict__ ei) {
    int e = blockIdx.x * blockDim.x + threadIdx.x;
    if (e < NE) atomicAdd(&g_cnt[ei[NE + e]], 1);
}

// block-level exclusive scan of g_cnt -> g_rowptr (partial), block totals -> g_part
__global__ __launch_bounds__(SCAN_TPB) void k_scan1() {
    __shared__ int warp_sums[16];
    int b = blockIdx.x, t = threadIdx.x;
    int base = b * SCAN_ELEMS + t * 4;
    int v[4]; int s = 0;
#pragma unroll
    for (int i = 0; i < 4; ++i) {
        int idx = base + i;
        int c = (idx < NN) ? g_cnt[idx] : 0;
        v[i] = s; s += c;
    }
    int lane = t & 31, w = t >> 5;
    int ps = s;
#pragma unroll
    for (int o = 1; o < 32; o <<= 1) {
        int x = __shfl_up_sync(0xFFFFFFFFu, ps, o);
        if (lane >= o) ps += x;
    }
    if (lane == 31) warp_sums[w] = ps;
    __syncthreads();
    if (w == 0) {
        int ws = (lane < 16) ? warp_sums[lane] : 0;
#pragma unroll
        for (int o = 1; o < 16; o <<= 1) {
            int x = __shfl_up_sync(0xFFFFFFFFu, ws, o);
            if (lane >= o) ws += x;
        }
        if (lane < 16) warp_sums[lane] = ws;  // inclusive
    }
    __syncthreads();
    int woff = (w > 0) ? warp_sums[w - 1] : 0;
    int ex = woff + ps - s;  // exclusive offset of this thread within block
#pragma unroll
    for (int i = 0; i < 4; ++i) {
        int idx = base + i;
        if (idx < NN) g_rowptr[idx] = ex + v[i];
    }
    if (t == SCAN_TPB - 1) g_part[b] = woff + ps;  // block total
}

__global__ void k_scan2() {  // tiny serial exclusive scan of 49 partials
    if (threadIdx.x == 0) {
        int run = 0;
#pragma unroll 1
        for (int b = 0; b < SCAN_NB; ++b) {
            int t = g_part[b]; g_part[b] = run; run += t;
        }
    }
}

__global__ void k_scan3() {  // add block offsets; init cursors; dinv
    int n = blockIdx.x * blockDim.x + threadIdx.x;
    if (n < NN) {
        int r = g_rowptr[n] + g_part[n / SCAN_ELEMS];
        g_rowptr[n] = r;
        g_cur[n] = r;
        g_dinv[n] = rsqrtf((float)g_cnt[n] + 1.0f);
    }
}

__global__ void k_fill(const int* __restrict__ ei) {
    int e = blockIdx.x * blockDim.x + threadIdx.x;
    if (e < NE) {
        int src = ei[e];
        int dst = ei[NE + e];
        int pos = atomicAdd(&g_cur[dst], 1);
        g_eidx[pos] = src;
    }
}

// ---------------- layer 0 GEMM: x[N,7] @ W0[7,128] -> g_hl -------------------
__global__ __launch_bounds__(256) void k_gemm0(const float* __restrict__ x,
                                               const float* __restrict__ W0) {
    int idx = blockIdx.x * blockDim.x + threadIdx.x;
    int n = idx >> 5;
    int cg = idx & 31;
    if (n >= NN) return;
    float4 acc = make_float4(0.f, 0.f, 0.f, 0.f);
    const float4* W4 = (const float4*)W0;
#pragma unroll
    for (int k = 0; k < 7; ++k) {
        float xv = __ldg(&x[n * 7 + k]);
        float4 w = __ldg(&W4[k * 32 + cg]);
        acc.x += xv * w.x; acc.y += xv * w.y; acc.z += xv * w.z; acc.w += xv * w.w;
    }
    ((float4*)g_hl)[(size_t)n * 32 + cg] = acc;
}

// ---------------- main GEMM: g_h[N,128] @ W[128,128] -> g_hl -----------------
__global__ __launch_bounds__(256) void k_gemm128(const float* __restrict__ W) {
    __shared__ float As[128 * 33];  // [row][k] padded
    __shared__ float Ws[32 * 128];  // [k][c]
    int tid = threadIdx.x;
    int row0 = blockIdx.x * 128;
    int ty = tid >> 4, tx = tid & 15;  // 16x16 thread grid

    float acc[8][8];
#pragma unroll
    for (int i = 0; i < 8; ++i)
#pragma unroll
        for (int j = 0; j < 8; ++j) acc[i][j] = 0.f;

    int lr = tid >> 3;             // 0..31
    int lk = (tid & 7) * 4;        // 0,4,...,28
    int wk = tid >> 5;             // 0..7
    int wc = (tid & 31) * 4;       // 0..124

    for (int kc = 0; kc < 4; ++kc) {
#pragma unroll
        for (int l = 0; l < 4; ++l) {
            int r = l * 32 + lr;
            int gr = row0 + r;
            float4 v = make_float4(0.f, 0.f, 0.f, 0.f);
            if (gr < NN) v = *(const float4*)&g_h[(size_t)gr * 128 + kc * 32 + lk];
            As[r * 33 + lk + 0] = v.x;
            As[r * 33 + lk + 1] = v.y;
            As[r * 33 + lk + 2] = v.z;
            As[r * 33 + lk + 3] = v.w;
        }
#pragma unroll
        for (int l = 0; l < 4; ++l) {
            int k = l * 8 + wk;
            *(float4*)&Ws[k * 128 + wc] = *(const float4*)&W[(kc * 32 + k) * 128 + wc];
        }
        __syncthreads();

#pragma unroll 8
        for (int k = 0; k < 32; ++k) {
            float a[8];
#pragma unroll
            for (int i = 0; i < 8; ++i) a[i] = As[(ty * 8 + i) * 33 + k];
            float w[8];
            *(float4*)&w[0] = *(const float4*)&Ws[k * 128 + tx * 8];
            *(float4*)&w[4] = *(const float4*)&Ws[k * 128 + tx * 8 + 4];
#pragma unroll
            for (int i = 0; i < 8; ++i)
#pragma unroll
                for (int j = 0; j < 8; ++j) acc[i][j] += a[i] * w[j];
        }
        __syncthreads();
    }

#pragma unroll
    for (int i = 0; i < 8; ++i) {
        int gr = row0 + ty * 8 + i;
        if (gr < NN) {
            *(float4*)&g_hl[(size_t)gr * 128 + tx * 8 + 0] =
                make_float4(acc[i][0], acc[i][1], acc[i][2], acc[i][3]);
            *(float4*)&g_hl[(size_t)gr * 128 + tx * 8 + 4] =
                make_float4(acc[i][4], acc[i][5], acc[i][6], acc[i][7]);
        }
    }
}

// ---------- fused gather-aggregate + bias + BN + ReLU -> g_h -----------------
// one warp per node; lane covers 4 channels (float4). No atomics.
__global__ __launch_bounds__(256) void k_aggr(const float* __restrict__ gamma,
                                              const float* __restrict__ beta,
                                              const float* __restrict__ mean,
                                              const float* __restrict__ var,
                                              const float* __restrict__ bias) {
    __shared__ float ss[128], st[128];
    int t = threadIdx.x;
    if (t < 128) {
        float s = gamma[t] * rsqrtf(var[t] + BN_EPS);
        ss[t] = s;
        st[t] = (bias[t] - mean[t]) * s + beta[t];
    }
    __syncthreads();

    int gw = (blockIdx.x * blockDim.x + t) >> 5;  // global warp = node
    int lane = t & 31;
    if (gw >= NN) return;
    int n = gw;

    float dn = __ldg(&g_dinv[n]);
    const float4* hl4 = (const float4*)g_hl;

    // self-loop contribution: hl[n] * dinv[n]^2
    float4 v = __ldg(&hl4[(size_t)n * 32 + lane]);
    float sn = dn * dn;
    v.x *= sn; v.y *= sn; v.z *= sn; v.w *= sn;

    int lo = __ldg(&g_rowptr[n]);
    int cnt = __ldg(&g_cnt[n]);
#pragma unroll 2
    for (int e = 0; e < cnt; ++e) {
        int src = __ldg(&g_eidx[lo + e]);           // broadcast across warp
        float nm = __ldg(&g_dinv[src]) * dn;
        float4 m = __ldg(&hl4[(size_t)src * 32 + lane]);
        v.x += m.x * nm; v.y += m.y * nm; v.z += m.z * nm; v.w += m.w * nm;
    }

    int c4 = lane * 4;
    float4 h;
    h.x = fmaxf(v.x * ss[c4 + 0] + st[c4 + 0], 0.f);
    h.y = fmaxf(v.y * ss[c4 + 1] + st[c4 + 1], 0.f);
    h.z = fmaxf(v.z * ss[c4 + 2] + st[c4 + 2], 0.f);
    h.w = fmaxf(v.w * ss[c4 + 3] + st[c4 + 3], 0.f);
    ((float4*)g_h)[(size_t)n * 32 + lane] = h;
}

// ---------------- mean pool per graph (batch is sorted) ----------------------
__global__ void k_pool(const int* __restrict__ batch) {
    int g = blockIdx.x;
    int c = threadIdx.x;  // 128 threads
    __shared__ int s_lo, s_hi;
    if (c == 0) {
        int lo = 0, hi = NN;
        while (lo < hi) { int m = (lo + hi) >> 1; if (batch[m] < g) lo = m + 1; else hi = m; }
        s_lo = lo;
        int l2 = lo, h2 = NN;
        while (l2 < h2) { int m = (l2 + h2) >> 1; if (batch[m] < g + 1) l2 = m + 1; else h2 = m; }
        s_hi = l2;
    }
    __syncthreads();
    int lo = s_lo, hi = s_hi;
    float sum = 0.f;
    for (int r = lo; r < hi; ++r) sum += g_h[(size_t)r * 128 + c];
    float cnt = (float)(hi - lo);
    g_lig[g * 128 + c] = sum / fmaxf(cnt, 1.0f);
}

// ---------------- pocket MLP: 28 -> 64 -> 64 --------------------------------
__global__ void k_pocket(const float* __restrict__ pocket,
                         const float* __restrict__ pw1, const float* __restrict__ pb1,
                         const float* __restrict__ pw2, const float* __restrict__ pb2) {
    __shared__ float z[64];
    int j = threadIdx.x;  // 64 threads
    float a = pb1[j];
#pragma unroll
    for (int k = 0; k < 28; ++k) a += pocket[k] * pw1[k * 64 + j];
    z[j] = fmaxf(a, 0.f);
    __syncthreads();
    float b = pb2[j];
#pragma unroll 8
    for (int k = 0; k < 64; ++k) b += z[k] * pw2[k * 64 + j];
    g_p[j] = b;
}

// ---------------- classifier: [lig|p] (192) -> 96 -> 1 ----------------------
__global__ void k_cls(const float* __restrict__ cw1, const float* __restrict__ cb1,
                      const float* __restrict__ cw2, const float* __restrict__ cb2,
                      float* __restrict__ out) {
    int g = blockIdx.x;
    int j = threadIdx.x;  // 96 threads
    __shared__ float emb[192];
    __shared__ float red[96];
    for (int k = j; k < 128; k += 96) emb[k] = g_lig[g * 128 + k];
    if (j < 64) emb[128 + j] = g_p[j];
    __syncthreads();
    float a = cb1[j];
#pragma unroll 8
    for (int k = 0; k < 192; ++k) a += emb[k] * cw1[k * 96 + j];
    red[j] = fmaxf(a, 0.f) * cw2[j];
    __syncthreads();
    if (j < 32) {
        float s = red[j] + red[j + 32] + red[j + 64];
#pragma unroll
        for (int o = 16; o > 0; o >>= 1) s += __shfl_down_sync(0xFFFFFFFFu, s, o);
        if (j == 0) out[g] = s + cb2[0];
    }
}

// ---------------------------------------------------------------------------
extern "C" void kernel_launch(void* const* d_in, const int* in_sizes, int n_in,
                              void* d_out, int out_size) {
    const float* x      = (const float*)d_in[0];
    const int*   ei     = (const int*)d_in[1];
    const int*   batch  = (const int*)d_in[2];
    const float* pocket = (const float*)d_in[3];
    const float* W0 = (const float*)d_in[4];
    const float* b0 = (const float*)d_in[5];
    const float* W1 = (const float*)d_in[6];
    const float* b1 = (const float*)d_in[7];
    const float* W2 = (const float*)d_in[8];
    const float* b2 = (const float*)d_in[9];
    const float* bn_gamma = (const float*)d_in[10];
    const float* bn_beta  = (const float*)d_in[11];
    const float* bn_mean  = (const float*)d_in[12];
    const float* bn_var   = (const float*)d_in[13];
    const float* pw1 = (const float*)d_in[14];
    const float* pb1 = (const float*)d_in[15];
    const float* pw2 = (const float*)d_in[16];
    const float* pb2 = (const float*)d_in[17];
    const float* cw1 = (const float*)d_in[18];
    const float* cb1 = (const float*)d_in[19];
    const float* cw2 = (const float*)d_in[20];
    const float* cb2 = (const float*)d_in[21];
    float* out = (float*)d_out;

    const int TPB = 256;
    int gN   = (NN + TPB - 1) / TPB;
    int gE   = (NE + TPB - 1) / TPB;
    int gN32 = (NN * 32 + TPB - 1) / TPB;   // 12500 (also = warps-per-node grid)
    int gG   = (NN + 127) / 128;

    // ---- CSR build + normalization (once per call) ----
    k_zero_cnt<<<gN, TPB>>>();
    k_hist<<<gE, TPB>>>(ei);
    k_scan1<<<SCAN_NB, SCAN_TPB>>>();
    k_scan2<<<1, 32>>>();
    k_scan3<<<gN, TPB>>>();
    k_fill<<<gE, TPB>>>(ei);

    // ---- layer 0 (in = 7) ----
    k_gemm0<<<gN32, TPB>>>(x, W0);
    k_aggr<<<gN32, TPB>>>(bn_gamma + 0 * HID, bn_beta + 0 * HID,
                          bn_mean + 0 * HID, bn_var + 0 * HID, b0);

    // ---- layer 1 ----
    k_gemm128<<<gG, TPB>>>(W1);
    k_aggr<<<gN32, TPB>>>(bn_gamma + 1 * HID, bn_beta + 1 * HID,
                          bn_mean + 1 * HID, bn_var + 1 * HID, b1);

    // ---- layer 2 ----
    k_gemm128<<<gG, TPB>>>(W2);
    k_aggr<<<gN32, TPB>>>(bn_gamma + 2 * HID, bn_beta + 2 * HID,
                          bn_mean + 2 * HID, bn_var + 2 * HID, b2);

    // ---- readout ----
    k_pool<<<NG, 128>>>(batch);
    k_pocket<<<1, 64>>>(pocket, pw1, pb1, pw2, pb2);
    k_cls<<<NG, 96>>>(cw1, cb1, cw2, cb2, out);
}

// round 14
// speedup vs baseline: 1.1084x; 1.1084x over previous
#include <cuda_runtime.h>
#include <cuda_bf16.h>

#define NN 100000
#define NE 600000
#define NG 256
#define HID 128
#define BN_EPS 1e-5f

// ---------------- scratch (device globals; no allocation allowed) ------------
__device__ float g_deg[NN];
__device__ float g_dinv[NN];
__device__ float g_hl[NN * HID];   // hl = h @ W
__device__ float g_agg[NN * HID];  // aggregated messages (pre-activation)
__device__ float g_lig[NG * HID];  // pooled per-graph embedding
__device__ float g_p[64];          // pocket MLP output

// vectorized global reduction (sm_90+, PTX ISA 8.1)
__device__ __forceinline__ void red_add_v4(float* addr, float4 v) {
    asm volatile("red.global.add.v4.f32 [%0], {%1,%2,%3,%4};"
                 :: "l"(addr), "f"(v.x), "f"(v.y), "f"(v.z), "f"(v.w)
                 : "memory");
}

// ---------------- degree / normalization ------------------------------------
__global__ void k_deg_init() {
    int n = blockIdx.x * blockDim.x + threadIdx.x;
    if (n < NN) g_deg[n] = 1.0f;  // self-loop
}

__global__ void k_deg_edges(const int* __restrict__ ei) {
    int e = blockIdx.x * blockDim.x + threadIdx.x;
    if (e < NE) atomicAdd(&g_deg[ei[NE + e]], 1.0f);
}

__global__ void k_dinv() {
    int n = blockIdx.x * blockDim.x + threadIdx.x;
    if (n < NN) g_dinv[n] = rsqrtf(g_deg[n]);
}

// ---------------- layer 0 GEMM: x[N,7] @ W0[7,128] --------------------------
// one warp per node row; lane handles 4 output channels.
// Epilogue writes g_hl and g_agg = hl * dinv^2 (self-loop init).
__global__ __launch_bounds__(256) void k_gemm0(const float* __restrict__ x,
                                               const float* __restrict__ W0) {
    int idx = blockIdx.x * blockDim.x + threadIdx.x;
    int n = idx >> 5;
    int cg = idx & 31;
    if (n >= NN) return;
    float4 acc = make_float4(0.f, 0.f, 0.f, 0.f);
    const float4* W4 = (const float4*)W0;
#pragma unroll
    for (int k = 0; k < 7; ++k) {
        float xv = __ldg(&x[n * 7 + k]);
        float4 w = __ldg(&W4[k * 32 + cg]);
        acc.x += xv * w.x; acc.y += xv * w.y; acc.z += xv * w.z; acc.w += xv * w.w;
    }
    float sn = g_dinv[n]; sn *= sn;
    ((float4*)g_hl)[(size_t)n * 32 + cg] = acc;
    ((float4*)g_agg)[(size_t)n * 32 + cg] =
        make_float4(acc.x * sn, acc.y * sn, acc.z * sn, acc.w * sn);
}

// ---------------- main GEMM with fused input activation ----------------------
// A = relu(g_agg * ss + st)  (prev layer's bias+BN+ReLU applied on load)
// C = A @ W ; epilogue writes g_hl and g_agg = C * dinv^2 (self-loop init).
// Safe: each block reads only its own 128 g_agg rows and overwrites them only
// in the epilogue (after all A loads).
__global__ __launch_bounds__(256) void k_gemm128(const float* __restrict__ W,
                                                 const float* __restrict__ gamma,
                                                 const float* __restrict__ beta,
                                                 const float* __restrict__ mean,
                                                 const float* __restrict__ var,
                                                 const float* __restrict__ bias) {
    __shared__ float As[128 * 33];  // [row][k] padded
    __shared__ float Ws[32 * 128];  // [k][c]
    __shared__ float ss[128], st[128];
    int tid = threadIdx.x;
    int row0 = blockIdx.x * 128;
    int ty = tid >> 4, tx = tid & 15;  // 16x16 thread grid

    if (tid < 128) {
        float s = gamma[tid] * rsqrtf(var[tid] + BN_EPS);
        ss[tid] = s;
        st[tid] = (bias[tid] - mean[tid]) * s + beta[tid];
    }
    __syncthreads();

    float acc[8][8];
#pragma unroll
    for (int i = 0; i < 8; ++i)
#pragma unroll
        for (int j = 0; j < 8; ++j) acc[i][j] = 0.f;

    int lr = tid >> 3;             // 0..31
    int lk = (tid & 7) * 4;        // 0,4,...,28
    int wk = tid >> 5;             // 0..7
    int wc = (tid & 31) * 4;       // 0..124

    for (int kc = 0; kc < 4; ++kc) {
        int c0 = kc * 32 + lk;     // channel of first loaded element
#pragma unroll
        for (int l = 0; l < 4; ++l) {
            int r = l * 32 + lr;
            int gr = row0 + r;
            float4 v = make_float4(0.f, 0.f, 0.f, 0.f);
            if (gr < NN) {
                float4 a = *(const float4*)&g_agg[(size_t)gr * 128 + c0];
                v.x = fmaxf(a.x * ss[c0 + 0] + st[c0 + 0], 0.f);
                v.y = fmaxf(a.y * ss[c0 + 1] + st[c0 + 1], 0.f);
                v.z = fmaxf(a.z * ss[c0 + 2] + st[c0 + 2], 0.f);
                v.w = fmaxf(a.w * ss[c0 + 3] + st[c0 + 3], 0.f);
            }
            As[r * 33 + lk + 0] = v.x;
            As[r * 33 + lk + 1] = v.y;
            As[r * 33 + lk + 2] = v.z;
            As[r * 33 + lk + 3] = v.w;
        }
#pragma unroll
        for (int l = 0; l < 4; ++l) {
            int k = l * 8 + wk;
            *(float4*)&Ws[k * 128 + wc] = *(const float4*)&W[(kc * 32 + k) * 128 + wc];
        }
        __syncthreads();

#pragma unroll 8
        for (int k = 0; k < 32; ++k) {
            float a[8];
#pragma unroll
            for (int i = 0; i < 8; ++i) a[i] = As[(ty * 8 + i) * 33 + k];
            float w[8];
            *(float4*)&w[0] = *(const float4*)&Ws[k * 128 + tx * 8];
            *(float4*)&w[4] = *(const float4*)&Ws[k * 128 + tx * 8 + 4];
#pragma unroll
            for (int i = 0; i < 8; ++i)
#pragma unroll
                for (int j = 0; j < 8; ++j) acc[i][j] += a[i] * w[j];
        }
        __syncthreads();
    }

#pragma unroll
    for (int i = 0; i < 8; ++i) {
        int gr = row0 + ty * 8 + i;
        if (gr < NN) {
            float sn = g_dinv[gr]; sn *= sn;
            float4 h0 = make_float4(acc[i][0], acc[i][1], acc[i][2], acc[i][3]);
            float4 h1 = make_float4(acc[i][4], acc[i][5], acc[i][6], acc[i][7]);
            *(float4*)&g_hl[(size_t)gr * 128 + tx * 8 + 0] = h0;
            *(float4*)&g_hl[(size_t)gr * 128 + tx * 8 + 4] = h1;
            *(float4*)&g_agg[(size_t)gr * 128 + tx * 8 + 0] =
                make_float4(h0.x * sn, h0.y * sn, h0.z * sn, h0.w * sn);
            *(float4*)&g_agg[(size_t)gr * 128 + tx * 8 + 4] =
                make_float4(h1.x * sn, h1.y * sn, h1.z * sn, h1.w * sn);
        }
    }
}

// ---------------- edge scatter: agg[dst] += hl[src] * dinv[src]*dinv[dst] ---
// one warp per edge; lane handles 4 channels (float4), vectorized red.add
__global__ __launch_bounds__(256) void k_edges(const int* __restrict__ ei) {
    int gt = blockIdx.x * blockDim.x + threadIdx.x;
    int e = gt >> 5;
    int lane = gt & 31;
    if (e >= NE) return;
    int src = __ldg(&ei[e]);
    int dst = __ldg(&ei[NE + e]);
    float nm = __ldg(&g_dinv[src]) * __ldg(&g_dinv[dst]);
    float4 v = __ldg(&((const float4*)g_hl)[(size_t)src * 32 + lane]);
    v.x *= nm; v.y *= nm; v.z *= nm; v.w *= nm;
    red_add_v4(&g_agg[(size_t)dst * 128 + lane * 4], v);
}

// ------- mean pool per graph with fused layer-2 bias+BN+ReLU -----------------
// batch is sorted -> binary search row range, no atomics.
__global__ void k_pool(const int* __restrict__ batch,
                       const float* __restrict__ gamma, const float* __restrict__ beta,
                       const float* __restrict__ mean, const float* __restrict__ var,
                       const float* __restrict__ bias) {
    int g = blockIdx.x;
    int c = threadIdx.x;  // 128 threads, c = channel
    __shared__ int s_lo, s_hi;
    if (c == 0) {
        int lo = 0, hi = NN;
        while (lo < hi) { int m = (lo + hi) >> 1; if (batch[m] < g) lo = m + 1; else hi = m; }
        s_lo = lo;
        int l2 = lo, h2 = NN;
        while (l2 < h2) { int m = (l2 + h2) >> 1; if (batch[m] < g + 1) l2 = m + 1; else h2 = m; }
        s_hi = l2;
    }
    float s = gamma[c] * rsqrtf(var[c] + BN_EPS);
    float t = (bias[c] - mean[c]) * s + beta[c];
    __syncthreads();
    int lo = s_lo, hi = s_hi;
    float sum = 0.f;
    for (int r = lo; r < hi; ++r)
        sum += fmaxf(g_agg[(size_t)r * 128 + c] * s + t, 0.f);
    float cnt = (float)(hi - lo);
    g_lig[g * 128 + c] = sum / fmaxf(cnt, 1.0f);
}

// ---------------- pocket MLP: 28 -> 64 -> 64 --------------------------------
__global__ void k_pocket(const float* __restrict__ pocket,
                         const float* __restrict__ pw1, const float* __restrict__ pb1,
                         const float* __restrict__ pw2, const float* __restrict__ pb2) {
    __shared__ float z[64];
    int j = threadIdx.x;  // 64 threads
    float a = pb1[j];
#pragma unroll
    for (int k = 0; k < 28; ++k) a += pocket[k] * pw1[k * 64 + j];
    z[j] = fmaxf(a, 0.f);
    __syncthreads();
    float b = pb2[j];
#pragma unroll 8
    for (int k = 0; k < 64; ++k) b += z[k] * pw2[k * 64 + j];
    g_p[j] = b;
}

// ---------------- classifier: [lig|p] (192) -> 96 -> 1 ----------------------
__global__ void k_cls(const float* __restrict__ cw1, const float* __restrict__ cb1,
                      const float* __restrict__ cw2, const float* __restrict__ cb2,
                      float* __restrict__ out) {
    int g = blockIdx.x;
    int j = threadIdx.x;  // 96 threads
    __shared__ float emb[192];
    __shared__ float red[96];
    for (int k = j; k < 128; k += 96) emb[k] = g_lig[g * 128 + k];
    if (j < 64) emb[128 + j] = g_p[j];
    __syncthreads();
    float a = cb1[j];
#pragma unroll 8
    for (int k = 0; k < 192; ++k) a += emb[k] * cw1[k * 96 + j];
    red[j] = fmaxf(a, 0.f) * cw2[j];
    __syncthreads();
    if (j < 32) {
        float s = red[j] + red[j + 32] + red[j + 64];
#pragma unroll
        for (int o = 16; o > 0; o >>= 1) s += __shfl_down_sync(0xFFFFFFFFu, s, o);
        if (j == 0) out[g] = s + cb2[0];
    }
}

// ---------------------------------------------------------------------------
extern "C" void kernel_launch(void* const* d_in, const int* in_sizes, int n_in,
                              void* d_out, int out_size) {
    const float* x      = (const float*)d_in[0];
    const int*   ei     = (const int*)d_in[1];
    const int*   batch  = (const int*)d_in[2];
    const float* pocket = (const float*)d_in[3];
    const float* W0 = (const float*)d_in[4];
    const float* b0 = (const float*)d_in[5];
    const float* W1 = (const float*)d_in[6];
    const float* b1 = (const float*)d_in[7];
    const float* W2 = (const float*)d_in[8];
    const float* b2 = (const float*)d_in[9];
    const float* bn_gamma = (const float*)d_in[10];
    const float* bn_beta  = (const float*)d_in[11];
    const float* bn_mean  = (const float*)d_in[12];
    const float* bn_var   = (const float*)d_in[13];
    const float* pw1 = (const float*)d_in[14];
    const float* pb1 = (const float*)d_in[15];
    const float* pw2 = (const float*)d_in[16];
    const float* pb2 = (const float*)d_in[17];
    const float* cw1 = (const float*)d_in[18];
    const float* cb1 = (const float*)d_in[19];
    const float* cw2 = (const float*)d_in[20];
    const float* cb2 = (const float*)d_in[21];
    float* out = (float*)d_out;

    const int TPB = 256;
    int gN   = (NN + TPB - 1) / TPB;
    int gE   = (NE + TPB - 1) / TPB;
    int gN32 = (NN * 32 + TPB - 1) / TPB;
    int gE32 = (NE * 32 + TPB - 1) / TPB;
    int gG   = (NN + 127) / 128;

    // normalization coefficients
    k_deg_init<<<gN, TPB>>>();
    k_deg_edges<<<gE, TPB>>>(ei);
    k_dinv<<<gN, TPB>>>();

    // layer 0 (in = 7): gemm -> scatter (agg holds pre-activation result)
    k_gemm0<<<gN32, TPB>>>(x, W0);
    k_edges<<<gE32, TPB>>>(ei);

    // layer 1: gemm applies layer-0 bias/BN/ReLU on input
    k_gemm128<<<gG, TPB>>>(W1, bn_gamma + 0 * HID, bn_beta + 0 * HID,
                           bn_mean + 0 * HID, bn_var + 0 * HID, b0);
    k_edges<<<gE32, TPB>>>(ei);

    // layer 2: gemm applies layer-1 bias/BN/ReLU on input
    k_gemm128<<<gG, TPB>>>(W2, bn_gamma + 1 * HID, bn_beta + 1 * HID,
                           bn_mean + 1 * HID, bn_var + 1 * HID, b1);
    k_edges<<<gE32, TPB>>>(ei);

    // readout: pool applies layer-2 bias/BN/ReLU on input
    k_pool<<<NG, 128>>>(batch, bn_gamma + 2 * HID, bn_beta + 2 * HID,
                        bn_mean + 2 * HID, bn_var + 2 * HID, b2);
    k_pocket<<<1, 64>>>(pocket, pw1, pb1, pw2, pb2);
    k_cls<<<NG, 96>>>(cw1, cb1, cw2, cb2, out);
}

// round 15
// speedup vs baseline: 1.2676x; 1.1437x over previous
#include <cuda_runtime.h>
#include <cuda_bf16.h>

#define NN 100000
#define NE 600000
#define NG 256
#define HID 128
#define BN_EPS 1e-5f

// ---------------- scratch (device globals; no allocation allowed) ------------
__device__ float g_deg[NN];
__device__ float g_dinv[NN];
__device__ float g_xa[NN * 8];     // aggregated 7-dim input features (padded to 8)
__device__ float g_hl[NN * HID];   // hl = h @ W
__device__ float g_agg[NN * HID];  // aggregated messages (pre-activation)
__device__ float g_lig[NG * HID];  // pooled per-graph embedding
__device__ float g_p[64];          // pocket MLP output

// vectorized global reduction (sm_90+, PTX ISA 8.1)
__device__ __forceinline__ void red_add_v4(float* addr, float4 v) {
    asm volatile("red.global.add.v4.f32 [%0], {%1,%2,%3,%4};"
                 :: "l"(addr), "f"(v.x), "f"(v.y), "f"(v.z), "f"(v.w)
                 : "memory");
}

// ---------------- degree / normalization ------------------------------------
__global__ void k_deg_init() {
    int n = blockIdx.x * blockDim.x + threadIdx.x;
    if (n < NN) g_deg[n] = 1.0f;  // self-loop
}

__global__ void k_deg_edges(const int* __restrict__ ei) {
    int e = blockIdx.x * blockDim.x + threadIdx.x;
    if (e < NE) atomicAdd(&g_deg[ei[NE + e]], 1.0f);
}

__global__ void k_dinv() {
    int n = blockIdx.x * blockDim.x + threadIdx.x;
    if (n < NN) g_dinv[n] = rsqrtf(g_deg[n]);
}

// ------- layer-0 feature aggregation on raw 7-dim x (exact reordering) -------
// xa[n] = x[n]*dinv[n]^2  (self-loop init, padded to 8 channels)
__global__ void k_xa_init(const float* __restrict__ x) {
    int n = blockIdx.x * blockDim.x + threadIdx.x;
    if (n >= NN) return;
    float d = g_dinv[n]; float d2 = d * d;
#pragma unroll
    for (int c = 0; c < 7; ++c) g_xa[n * 8 + c] = x[n * 7 + c] * d2;
    g_xa[n * 8 + 7] = 0.f;
}

// xa[dst] += x[src] * dinv[src]*dinv[dst]; 2 threads per edge (4 channels each)
__global__ __launch_bounds__(256) void k_xa_edges(const float* __restrict__ x,
                                                  const int* __restrict__ ei) {
    int t = blockIdx.x * blockDim.x + threadIdx.x;
    int e = t >> 1;
    int half = t & 1;
    if (e >= NE) return;
    int src = __ldg(&ei[e]);
    int dst = __ldg(&ei[NE + e]);
    float nm = __ldg(&g_dinv[src]) * __ldg(&g_dinv[dst]);
    float4 v;
    if (half == 0) {
        v.x = __ldg(&x[src * 7 + 0]) * nm;
        v.y = __ldg(&x[src * 7 + 1]) * nm;
        v.z = __ldg(&x[src * 7 + 2]) * nm;
        v.w = __ldg(&x[src * 7 + 3]) * nm;
    } else {
        v.x = __ldg(&x[src * 7 + 4]) * nm;
        v.y = __ldg(&x[src * 7 + 5]) * nm;
        v.z = __ldg(&x[src * 7 + 6]) * nm;
        v.w = 0.f;
    }
    red_add_v4(&g_xa[(size_t)dst * 8 + half * 4], v);
}

// ---------------- layer 0 GEMM: xa[N,7] @ W0[7,128] -> g_agg -----------------
// one warp per node row; lane handles 4 output channels.
__global__ __launch_bounds__(256) void k_gemm0(const float* __restrict__ W0) {
    int idx = blockIdx.x * blockDim.x + threadIdx.x;
    int n = idx >> 5;
    int cg = idx & 31;
    if (n >= NN) return;
    float4 acc = make_float4(0.f, 0.f, 0.f, 0.f);
    const float4* W4 = (const float4*)W0;
#pragma unroll
    for (int k = 0; k < 7; ++k) {
        float xv = g_xa[(size_t)n * 8 + k];
        float4 w = __ldg(&W4[k * 32 + cg]);
        acc.x += xv * w.x; acc.y += xv * w.y; acc.z += xv * w.z; acc.w += xv * w.w;
    }
    ((float4*)g_agg)[(size_t)n * 32 + cg] = acc;
}

// ---------------- main GEMM with fused input activation ----------------------
// A = relu(g_agg * ss + st)  (prev layer's bias+BN+ReLU applied on load)
// C = A @ W ; epilogue writes g_hl and g_agg = C * dinv^2 (self-loop init).
__global__ __launch_bounds__(256) void k_gemm128(const float* __restrict__ W,
                                                 const float* __restrict__ gamma,
                                                 const float* __restrict__ beta,
                                                 const float* __restrict__ mean,
                                                 const float* __restrict__ var,
                                                 const float* __restrict__ bias) {
    __shared__ float As[128 * 33];  // [row][k] padded
    __shared__ float Ws[32 * 128];  // [k][c]
    __shared__ float ss[128], st[128];
    int tid = threadIdx.x;
    int row0 = blockIdx.x * 128;
    int ty = tid >> 4, tx = tid & 15;  // 16x16 thread grid

    if (tid < 128) {
        float s = gamma[tid] * rsqrtf(var[tid] + BN_EPS);
        ss[tid] = s;
        st[tid] = (bias[tid] - mean[tid]) * s + beta[tid];
    }
    __syncthreads();

    float acc[8][8];
#pragma unroll
    for (int i = 0; i < 8; ++i)
#pragma unroll
        for (int j = 0; j < 8; ++j) acc[i][j] = 0.f;

    int lr = tid >> 3;             // 0..31
    int lk = (tid & 7) * 4;        // 0,4,...,28
    int wk = tid >> 5;             // 0..7
    int wc = (tid & 31) * 4;       // 0..124

    for (int kc = 0; kc < 4; ++kc) {
        int c0 = kc * 32 + lk;     // channel of first loaded element
#pragma unroll
        for (int l = 0; l < 4; ++l) {
            int r = l * 32 + lr;
            int gr = row0 + r;
            float4 v = make_float4(0.f, 0.f, 0.f, 0.f);
            if (gr < NN) {
                float4 a = *(const float4*)&g_agg[(size_t)gr * 128 + c0];
                v.x = fmaxf(a.x * ss[c0 + 0] + st[c0 + 0], 0.f);
                v.y = fmaxf(a.y * ss[c0 + 1] + st[c0 + 1], 0.f);
                v.z = fmaxf(a.z * ss[c0 + 2] + st[c0 + 2], 0.f);
                v.w = fmaxf(a.w * ss[c0 + 3] + st[c0 + 3], 0.f);
            }
            As[r * 33 + lk + 0] = v.x;
            As[r * 33 + lk + 1] = v.y;
            As[r * 33 + lk + 2] = v.z;
            As[r * 33 + lk + 3] = v.w;
        }
#pragma unroll
        for (int l = 0; l < 4; ++l) {
            int k = l * 8 + wk;
            *(float4*)&Ws[k * 128 + wc] = *(const float4*)&W[(kc * 32 + k) * 128 + wc];
        }
        __syncthreads();

#pragma unroll 8
        for (int k = 0; k < 32; ++k) {
            float a[8];
#pragma unroll
            for (int i = 0; i < 8; ++i) a[i] = As[(ty * 8 + i) * 33 + k];
            float w[8];
            *(float4*)&w[0] = *(const float4*)&Ws[k * 128 + tx * 8];
            *(float4*)&w[4] = *(const float4*)&Ws[k * 128 + tx * 8 + 4];
#pragma unroll
            for (int i = 0; i < 8; ++i)
#pragma unroll
                for (int j = 0; j < 8; ++j) acc[i][j] += a[i] * w[j];
        }
        __syncthreads();
    }

#pragma unroll
    for (int i = 0; i < 8; ++i) {
        int gr = row0 + ty * 8 + i;
        if (gr < NN) {
            float sn = g_dinv[gr]; sn *= sn;
            float4 h0 = make_float4(acc[i][0], acc[i][1], acc[i][2], acc[i][3]);
            float4 h1 = make_float4(acc[i][4], acc[i][5], acc[i][6], acc[i][7]);
            *(float4*)&g_hl[(size_t)gr * 128 + tx * 8 + 0] = h0;
            *(float4*)&g_hl[(size_t)gr * 128 + tx * 8 + 4] = h1;
            *(float4*)&g_agg[(size_t)gr * 128 + tx * 8 + 0] =
                make_float4(h0.x * sn, h0.y * sn, h0.z * sn, h0.w * sn);
            *(float4*)&g_agg[(size_t)gr * 128 + tx * 8 + 4] =
                make_float4(h1.x * sn, h1.y * sn, h1.z * sn, h1.w * sn);
        }
    }
}

// ---------------- edge scatter: agg[dst] += hl[src] * dinv[src]*dinv[dst] ---
// one warp per edge; lane handles 4 channels (float4), vectorized red.add
__global__ __launch_bounds__(256) void k_edges(const int* __restrict__ ei) {
    int gt = blockIdx.x * blockDim.x + threadIdx.x;
    int e = gt >> 5;
    int lane = gt & 31;
    if (e >= NE) return;
    int src = __ldg(&ei[e]);
    int dst = __ldg(&ei[NE + e]);
    float nm = __ldg(&g_dinv[src]) * __ldg(&g_dinv[dst]);
    float4 v = __ldg(&((const float4*)g_hl)[(size_t)src * 32 + lane]);
    v.x *= nm; v.y *= nm; v.z *= nm; v.w *= nm;
    red_add_v4(&g_agg[(size_t)dst * 128 + lane * 4], v);
}

// ------- mean pool per graph with fused layer-2 bias+BN+ReLU -----------------
__global__ void k_pool(const int* __restrict__ batch,
                       const float* __restrict__ gamma, const float* __restrict__ beta,
                       const float* __restrict__ mean, const float* __restrict__ var,
                       const float* __restrict__ bias) {
    int g = blockIdx.x;
    int c = threadIdx.x;  // 128 threads, c = channel
    __shared__ int s_lo, s_hi;
    if (c == 0) {
        int lo = 0, hi = NN;
        while (lo < hi) { int m = (lo + hi) >> 1; if (batch[m] < g) lo = m + 1; else hi = m; }
        s_lo = lo;
        int l2 = lo, h2 = NN;
        while (l2 < h2) { int m = (l2 + h2) >> 1; if (batch[m] < g + 1) l2 = m + 1; else h2 = m; }
        s_hi = l2;
    }
    float s = gamma[c] * rsqrtf(var[c] + BN_EPS);
    float t = (bias[c] - mean[c]) * s + beta[c];
    __syncthreads();
    int lo = s_lo, hi = s_hi;
    float sum = 0.f;
    for (int r = lo; r < hi; ++r)
        sum += fmaxf(g_agg[(size_t)r * 128 + c] * s + t, 0.f);
    float cnt = (float)(hi - lo);
    g_lig[g * 128 + c] = sum / fmaxf(cnt, 1.0f);
}

// ---------------- pocket MLP: 28 -> 64 -> 64 --------------------------------
__global__ void k_pocket(const float* __restrict__ pocket,
                         const float* __restrict__ pw1, const float* __restrict__ pb1,
                         const float* __restrict__ pw2, const float* __restrict__ pb2) {
    __shared__ float z[64];
    int j = threadIdx.x;  // 64 threads
    float a = pb1[j];
#pragma unroll
    for (int k = 0; k < 28; ++k) a += pocket[k] * pw1[k * 64 + j];
    z[j] = fmaxf(a, 0.f);
    __syncthreads();
    float b = pb2[j];
#pragma unroll 8
    for (int k = 0; k < 64; ++k) b += z[k] * pw2[k * 64 + j];
    g_p[j] = b;
}

// ---------------- classifier: [lig|p] (192) -> 96 -> 1 ----------------------
__global__ void k_cls(const float* __restrict__ cw1, const float* __restrict__ cb1,
                      const float* __restrict__ cw2, const float* __restrict__ cb2,
                      float* __restrict__ out) {
    int g = blockIdx.x;
    int j = threadIdx.x;  // 96 threads
    __shared__ float emb[192];
    __shared__ float red[96];
    for (int k = j; k < 128; k += 96) emb[k] = g_lig[g * 128 + k];
    if (j < 64) emb[128 + j] = g_p[j];
    __syncthreads();
    float a = cb1[j];
#pragma unroll 8
    for (int k = 0; k < 192; ++k) a += emb[k] * cw1[k * 96 + j];
    red[j] = fmaxf(a, 0.f) * cw2[j];
    __syncthreads();
    if (j < 32) {
        float s = red[j] + red[j + 32] + red[j + 64];
#pragma unroll
        for (int o = 16; o > 0; o >>= 1) s += __shfl_down_sync(0xFFFFFFFFu, s, o);
        if (j == 0) out[g] = s + cb2[0];
    }
}

// ---------------------------------------------------------------------------
extern "C" void kernel_launch(void* const* d_in, const int* in_sizes, int n_in,
                              void* d_out, int out_size) {
    const float* x      = (const float*)d_in[0];
    const int*   ei     = (const int*)d_in[1];
    const int*   batch  = (const int*)d_in[2];
    const float* pocket = (const float*)d_in[3];
    const float* W0 = (const float*)d_in[4];
    const float* b0 = (const float*)d_in[5];
    const float* W1 = (const float*)d_in[6];
    const float* b1 = (const float*)d_in[7];
    const float* W2 = (const float*)d_in[8];
    const float* b2 = (const float*)d_in[9];
    const float* bn_gamma = (const float*)d_in[10];
    const float* bn_beta  = (const float*)d_in[11];
    const float* bn_mean  = (const float*)d_in[12];
    const float* bn_var   = (const float*)d_in[13];
    const float* pw1 = (const float*)d_in[14];
    const float* pb1 = (const float*)d_in[15];
    const float* pw2 = (const float*)d_in[16];
    const float* pb2 = (const float*)d_in[17];
    const float* cw1 = (const float*)d_in[18];
    const float* cb1 = (const float*)d_in[19];
    const float* cw2 = (const float*)d_in[20];
    const float* cb2 = (const float*)d_in[21];
    float* out = (float*)d_out;

    const int TPB = 256;
    int gN   = (NN + TPB - 1) / TPB;
    int gE   = (NE + TPB - 1) / TPB;
    int gE2  = (NE * 2 + TPB - 1) / TPB;
    int gN32 = (NN * 32 + TPB - 1) / TPB;
    int gE32 = (NE * 32 + TPB - 1) / TPB;
    int gG   = (NN + 127) / 128;

    // normalization coefficients
    k_deg_init<<<gN, TPB>>>();
    k_deg_edges<<<gE, TPB>>>(ei);
    k_dinv<<<gN, TPB>>>();

    // layer 0: aggregate raw 7-dim features first (A(xW) == (Ax)W), then GEMM
    k_xa_init<<<gN, TPB>>>(x);
    k_xa_edges<<<gE2, TPB>>>(x, ei);
    k_gemm0<<<gN32, TPB>>>(W0);

    // layer 1: gemm applies layer-0 bias/BN/ReLU on input
    k_gemm128<<<gG, TPB>>>(W1, bn_gamma + 0 * HID, bn_beta + 0 * HID,
                           bn_mean + 0 * HID, bn_var + 0 * HID, b0);
    k_edges<<<gE32, TPB>>>(ei);

    // layer 2: gemm applies layer-1 bias/BN/ReLU on input
    k_gemm128<<<gG, TPB>>>(W2, bn_gamma + 1 * HID, bn_beta + 1 * HID,
                           bn_mean + 1 * HID, bn_var + 1 * HID, b1);
    k_edges<<<gE32, TPB>>>(ei);

    // readout: pool applies layer-2 bias/BN/ReLU on input
    k_pool<<<NG, 128>>>(batch, bn_gamma + 2 * HID, bn_beta + 2 * HID,
                        bn_mean + 2 * HID, bn_var + 2 * HID, b2);
    k_pocket<<<1, 64>>>(pocket, pw1, pb1, pw2, pb2);
    k_cls<<<NG, 96>>>(cw1, cb1, cw2, cb2, out);
}